// round 12
// baseline (speedup 1.0000x reference)
#include <cuda_runtime.h>
#include <math.h>

#define HIN   1536
#define BM    128
#define BK    8
#define KSPL  768            // K per split
#define NT    (KSPL / BK)    // 96 k-tiles per split
#define NTHR  128

#define BASE1 524288
#define BASE2 786432
#define BASE3 1048576
#define TOTE  1179648        // 8192*144

__device__ float g_part[2][TOTE];   // split-K partial sums (fp32)

using u64 = unsigned long long;

__device__ __forceinline__ u64 pk2(float lo, float hi) {
    u64 r; asm("mov.b64 %0, {%1, %2};" : "=l"(r) : "f"(lo), "f"(hi)); return r;
}
__device__ __forceinline__ void upk2(u64 v, float& lo, float& hi) {
    asm("mov.b64 {%0, %1}, %2;" : "=f"(lo), "=f"(hi) : "l"(v));
}
__device__ __forceinline__ u64 ffma2(u64 a, u64 b, u64 c) {
#if defined(__CUDA_ARCH__) && (__CUDA_ARCH__ >= 1000)
    u64 d; asm("fma.rn.f32x2 %0, %1, %2, %3;" : "=l"(d) : "l"(a), "l"(b), "l"(c)); return d;
#else
    float al, ah, bl, bh, cl, ch;
    upk2(a, al, ah); upk2(b, bl, bh); upk2(c, cl, ch);
    return pk2(fmaf(al, bl, cl), fmaf(ah, bh, ch));
#endif
}

// A smem: phys = k*BM + (r ^ ((k>>1)<<3)).
//  stores (k = c*4+u, c=tid&1): bank = r0[0:3]^((u>>1)<<3) | c<<4 -> 32 distinct, CF.
//  reads: quads rows ty*8+{0..3}(+4) ^ msk, msk bits 3-4 -> 16B-contiguous, 4 bcast groups.
// B smem: D=64 padded phys = n + ((n>>5)<<2), row stride 72 -> CF float4 reads.
template<int D> __device__ __forceinline__ int bswz(int n) {
    if constexpr (D == 64) return n + ((n >> 5) << 2);
    else return n;
}
template<int D> constexpr int BROW = (D == 64) ? 72 : D;

template<int D>
__device__ __forceinline__ void run_gemm(
    const float* __restrict__ X, const float* __restrict__ W,
    int tile, int split, float* __restrict__ AsF, float* __restrict__ Bk,
    float* __restrict__ outp)
{
    constexpr int TN = D / 8;             // 8 / 4 / 2
    constexpr int NB = (BK * D) / NTHR;   // 4 / 2 / 1
    const int tid = threadIdx.x;
    const int tx  = tid & 7;
    const int ty  = tid >> 3;             // rows ty*8 .. ty*8+7
    const int r0  = tid >> 1;             // A-load row base (+64)
    const int c2  = tid & 1;              // A-load k-chunk (0/1)
    const int kbase = split * KSPL;
    const float* __restrict__ Ablk = X + (size_t)tile * BM * HIN + kbase;
    const float* __restrict__ Wб = W + (size_t)kbase * D;

    float4 va[2];
    float  vb[NB];
    u64 acc[4][TN];
#pragma unroll
    for (int i = 0; i < 4; ++i)
#pragma unroll
        for (int j = 0; j < TN; ++j) acc[i][j] = 0ull;

    // prologue: load tile 0
#pragma unroll
    for (int p = 0; p < 2; ++p)
        va[p] = *(const float4*)(Ablk + (size_t)(r0 + p * 64) * HIN + c2 * 4);
#pragma unroll
    for (int q = 0; q < NB; ++q) vb[q] = Wб[tid + q * NTHR];

    for (int t = 0; t < NT; ++t) {
        // store staged tile
#pragma unroll
        for (int p = 0; p < 2; ++p) {
            const int r = r0 + p * 64;
            const float* vp = (const float*)&va[p];
#pragma unroll
            for (int u = 0; u < 4; ++u) {
                const int kk = c2 * 4 + u;
                AsF[kk * BM + (r ^ ((kk >> 1) << 3))] = vp[u];
            }
        }
#pragma unroll
        for (int q = 0; q < NB; ++q) {
            int idx = tid + q * NTHR;
            int kk = idx / D, nn = idx % D;
            Bk[kk * BROW<D> + bswz<D>(nn)] = vb[q];
        }
        __syncthreads();

        const bool more = (t + 1 < NT);
        const int k0n = (t + 1) * BK;
        if (more) {
#pragma unroll
            for (int p = 0; p < 2; ++p)
                va[p] = *(const float4*)(Ablk + (size_t)(r0 + p * 64) * HIN + k0n + c2 * 4);
#pragma unroll
            for (int q = 0; q < NB; ++q) vb[q] = Wб[(size_t)k0n * D + tid + q * NTHR];
        }

#pragma unroll
        for (int k = 0; k < BK; ++k) {
            const int msk = (k >> 1) << 3;
            u64 bd[TN];
            const float* brow = Bk + k * BROW<D> + bswz<D>(tx * TN);
            if constexpr (TN == 8) {
                float4 b0 = *(const float4*)(brow);
                float4 b1 = *(const float4*)(brow + 4);
                bd[0] = pk2(b0.x, b0.x); bd[1] = pk2(b0.y, b0.y);
                bd[2] = pk2(b0.z, b0.z); bd[3] = pk2(b0.w, b0.w);
                bd[4] = pk2(b1.x, b1.x); bd[5] = pk2(b1.y, b1.y);
                bd[6] = pk2(b1.z, b1.z); bd[7] = pk2(b1.w, b1.w);
            } else if constexpr (TN == 4) {
                float4 b0 = *(const float4*)(brow);
                bd[0] = pk2(b0.x, b0.x); bd[1] = pk2(b0.y, b0.y);
                bd[2] = pk2(b0.z, b0.z); bd[3] = pk2(b0.w, b0.w);
            } else {
                float2 b0 = *(const float2*)(brow);
                bd[0] = pk2(b0.x, b0.x); bd[1] = pk2(b0.y, b0.y);
            }
            const float* Ar = AsF + k * BM;
            ulonglong2 a0 = *(const ulonglong2*)(Ar + ((ty * 8)     ^ msk));
            ulonglong2 a1 = *(const ulonglong2*)(Ar + ((ty * 8 + 4) ^ msk));
            u64 ap[4] = { a0.x, a0.y, a1.x, a1.y };
#pragma unroll
            for (int j = 0; j < TN; ++j)
#pragma unroll
                for (int i = 0; i < 4; ++i)
                    acc[i][j] = ffma2(ap[i], bd[j], acc[i][j]);
        }
        __syncthreads();
    }

    // store partials (pure fp32, no epilogue math)
#pragma unroll
    for (int r = 0; r < 8; ++r) {
        float v[TN];
#pragma unroll
        for (int j = 0; j < TN; ++j) {
            float lo, hi; upk2(acc[r >> 1][j], lo, hi);
            v[j] = (r & 1) ? hi : lo;
        }
        float* dst = outp + (size_t)(tile * BM + ty * 8 + r) * D + tx * TN;
        if constexpr (TN == 8) {
            *(float4*)dst       = make_float4(v[0], v[1], v[2], v[3]);
            *(float4*)(dst + 4) = make_float4(v[4], v[5], v[6], v[7]);
        } else if constexpr (TN == 4) {
            *(float4*)dst = make_float4(v[0], v[1], v[2], v[3]);
        } else {
            *(float2*)dst = make_float2(v[0], v[1]);
        }
    }
}

__global__ void __launch_bounds__(NTHR, 4) gemm_splitk(
    const float* __restrict__ x0, const float* __restrict__ w0,
    const float* __restrict__ x1, const float* __restrict__ w1,
    const float* __restrict__ x2, const float* __restrict__ w2,
    const float* __restrict__ x3, const float* __restrict__ w3)
{
    __shared__ __align__(16) float AsF[BK * BM];     // 4 KB
    __shared__ __align__(16) float Bk[BK * 72];      // 2.25 KB
    const int bid   = blockIdx.x;                    // 512 blocks
    const int s     = bid & 3;                       // stream interleave
    const int split = (bid >> 2) & 1;
    const int tile  = bid >> 3;                      // 64 tiles per stream
    float* part = g_part[split];
    if (s == 0)      run_gemm<64>(x0, w0, tile, split, AsF, Bk, part);
    else if (s == 1) run_gemm<32>(x1, w1, tile, split, AsF, Bk, part + BASE1);
    else if (s == 2) run_gemm<32>(x2, w2, tile, split, AsF, Bk, part + BASE2);
    else             run_gemm<16>(x3, w3, tile, split, AsF, Bk, part + BASE3);
}

// One warp per output row: sum partials + bias -> exact GELU -> LN -> gamma/beta.
__global__ void __launch_bounds__(256) combine_ln(
    const float* __restrict__ b0, const float* __restrict__ g0, const float* __restrict__ t0,
    const float* __restrict__ b1, const float* __restrict__ g1, const float* __restrict__ t1,
    const float* __restrict__ b2, const float* __restrict__ g2, const float* __restrict__ t2,
    const float* __restrict__ b3, const float* __restrict__ g3, const float* __restrict__ t3,
    float* __restrict__ out)
{
    const int rid  = blockIdx.x * 8 + (threadIdx.x >> 5);   // 0..32767
    const int lane = threadIdx.x & 31;
    const int s = rid >> 13;
    const int m = rid & 8191;
    int D; size_t base; const float *Bp, *Gp, *Tp;
    if (s == 0)      { D = 64; base = 0;     Bp = b0; Gp = g0; Tp = t0; }
    else if (s == 1) { D = 32; base = BASE1; Bp = b1; Gp = g1; Tp = t1; }
    else if (s == 2) { D = 32; base = BASE2; Bp = b2; Gp = g2; Tp = t2; }
    else             { D = 16; base = BASE3; Bp = b3; Gp = g3; Tp = t3; }
    const size_t off = base + (size_t)m * D;

    const bool act0 = lane < D;
    const bool act1 = (D == 64);
    const int  c1   = lane + 32;
    float v0 = 0.f, v1 = 0.f;
    if (act0) {
        float x = g_part[0][off + lane] + g_part[1][off + lane] + Bp[lane];
        v0 = 0.5f * x * (1.0f + erff(x * 0.7071067811865475f));
    }
    if (act1) {
        float x = g_part[0][off + c1] + g_part[1][off + c1] + Bp[c1];
        v1 = 0.5f * x * (1.0f + erff(x * 0.7071067811865475f));
    }
    float ss = v0 + v1, s2 = v0 * v0 + v1 * v1;
#pragma unroll
    for (int o = 16; o >= 1; o >>= 1) {
        ss += __shfl_xor_sync(0xffffffffu, ss, o);
        s2 += __shfl_xor_sync(0xffffffffu, s2, o);
    }
    const float invD = 1.0f / (float)D;
    float mu  = ss * invD;
    float var = fmaxf(s2 * invD - mu * mu, 0.0f);
    float rs  = rsqrtf(var + 1e-5f);
    if (act0) out[off + lane] = (v0 - mu) * rs * Gp[lane] + Tp[lane];
    if (act1) out[off + c1]   = (v1 - mu) * rs * Gp[c1]   + Tp[c1];
}

extern "C" void kernel_launch(void* const* d_in, const int* in_sizes, int n_in,
                              void* d_out, int out_size)
{
    const float* x0 = (const float*)d_in[0];
    const float* w0 = (const float*)d_in[1];
    const float* b0 = (const float*)d_in[2];
    const float* g0 = (const float*)d_in[3];
    const float* t0 = (const float*)d_in[4];
    const float* x1 = (const float*)d_in[5];
    const float* w1 = (const float*)d_in[6];
    const float* b1 = (const float*)d_in[7];
    const float* g1 = (const float*)d_in[8];
    const float* t1 = (const float*)d_in[9];
    const float* x2 = (const float*)d_in[10];
    const float* w2 = (const float*)d_in[11];
    const float* b2 = (const float*)d_in[12];
    const float* g2 = (const float*)d_in[13];
    const float* t2 = (const float*)d_in[14];
    const float* x3 = (const float*)d_in[15];
    const float* w3 = (const float*)d_in[16];
    const float* b3 = (const float*)d_in[17];
    const float* g3 = (const float*)d_in[18];
    const float* t3 = (const float*)d_in[19];
    float* out = (float*)d_out;

    // Kernel 1: split-K GEMM, 512 blocks x 128 threads (streams interleaved)
    gemm_splitk<<<512, NTHR>>>(x0, w0, x1, w1, x2, w2, x3, w3);
    // Kernel 2: combine + bias + GELU + LayerNorm, one warp per row
    combine_ln<<<4096, 256>>>(b0, g0, t0, b1, g1, t1, b2, g2, t2, b3, g3, t3, out);
}

// round 13
// speedup vs baseline: 1.2363x; 1.2363x over previous
#include <cuda_runtime.h>
#include <math.h>

#define HIN   1536
#define BM    128
#define BK    16
#define KSPL  768            // K per split
#define NT    (KSPL / BK)    // 48 k-tiles per split
#define NTHR  128

#define BASE1 524288
#define BASE2 786432
#define BASE3 1048576
#define TOTE  1179648        // 8192*144

__device__ float g_part[2][TOTE];   // split-K partial sums (fp32)

using u64 = unsigned long long;

__device__ __forceinline__ u64 pk2(float lo, float hi) {
    u64 r; asm("mov.b64 %0, {%1, %2};" : "=l"(r) : "f"(lo), "f"(hi)); return r;
}
__device__ __forceinline__ void upk2(u64 v, float& lo, float& hi) {
    asm("mov.b64 {%0, %1}, %2;" : "=f"(lo), "=f"(hi) : "l"(v));
}
__device__ __forceinline__ u64 ffma2(u64 a, u64 b, u64 c) {
#if defined(__CUDA_ARCH__) && (__CUDA_ARCH__ >= 1000)
    u64 d; asm("fma.rn.f32x2 %0, %1, %2, %3;" : "=l"(d) : "l"(a), "l"(b), "l"(c)); return d;
#else
    float al, ah, bl, bh, cl, ch;
    upk2(a, al, ah); upk2(b, bl, bh); upk2(c, cl, ch);
    return pk2(fmaf(al, bl, cl), fmaf(ah, bh, ch));
#endif
}

// A smem: phys = k*BM + (r ^ ((k>>2)<<3)) — R11's proven BK=16 swizzle.
//  stores: bank = r[0:2] | (r[3:4]^c4) -> 32 distinct, conflict-free
//  reads: 4-row quads 16B-contiguous; 4 bcast groups/warp at rows {0,8,16,24} mod 32.
// B smem: D=64 padded phys = n + ((n>>5)<<2), row stride 72 -> conflict-free float4.
template<int D> __device__ __forceinline__ int bswz(int n) {
    if constexpr (D == 64) return n + ((n >> 5) << 2);
    else return n;
}
template<int D> constexpr int BROW = (D == 64) ? 72 : D;

template<int D>
__device__ __forceinline__ void run_gemm(
    const float* __restrict__ X, const float* __restrict__ W,
    int tile, int split, float* __restrict__ AsF, float* __restrict__ Bk,
    float* __restrict__ outp)
{
    constexpr int TN = D / 8;             // 8 / 4 / 2
    constexpr int NB = (BK * D) / NTHR;   // 8 / 4 / 2
    const int tid = threadIdx.x;
    const int tx  = tid & 7;              // n-group (8)
    const int ty  = tid >> 3;             // m-group (16): rows ty*8 .. ty*8+7
    const int r0  = tid >> 2;             // A-load row base (+p*32)
    const int c4  = tid & 3;              // A-load k-chunk
    const int kbase = split * KSPL;
    const float* __restrict__ Ablk = X + (size_t)tile * BM * HIN + kbase;
    const float* __restrict__ Wk   = W + (size_t)kbase * D;

    float4 va[4];
    float  vb[NB];
    u64 acc[4][TN];
#pragma unroll
    for (int i = 0; i < 4; ++i)
#pragma unroll
        for (int j = 0; j < TN; ++j) acc[i][j] = 0ull;

    // prologue: load tile 0
#pragma unroll
    for (int p = 0; p < 4; ++p)
        va[p] = *(const float4*)(Ablk + (size_t)(r0 + p * 32) * HIN + c4 * 4);
#pragma unroll
    for (int q = 0; q < NB; ++q) vb[q] = Wk[tid + q * NTHR];

    for (int t = 0; t < NT; ++t) {
        // store staged tile to smem
#pragma unroll
        for (int p = 0; p < 4; ++p) {
            const int r = r0 + p * 32;
            const float* vp = (const float*)&va[p];
#pragma unroll
            for (int u = 0; u < 4; ++u)
                AsF[(c4 * 4 + u) * BM + (r ^ (c4 << 3))] = vp[u];
        }
#pragma unroll
        for (int q = 0; q < NB; ++q) {
            int idx = tid + q * NTHR;
            int kk = idx / D, nn = idx % D;
            Bk[kk * BROW<D> + bswz<D>(nn)] = vb[q];
        }
        __syncthreads();

        // prefetch next tile into registers (hidden under compute)
        const bool more = (t + 1 < NT);
        const int k0n = (t + 1) * BK;
        if (more) {
#pragma unroll
            for (int p = 0; p < 4; ++p)
                va[p] = *(const float4*)(Ablk + (size_t)(r0 + p * 32) * HIN + k0n + c4 * 4);
#pragma unroll
            for (int q = 0; q < NB; ++q) vb[q] = Wk[(size_t)k0n * D + tid + q * NTHR];
        }

        // compute BK k-steps
#pragma unroll
        for (int k = 0; k < BK; ++k) {
            const int msk = (k >> 2) << 3;
            u64 bd[TN];
            const float* brow = Bk + k * BROW<D> + bswz<D>(tx * TN);
            if constexpr (TN == 8) {
                float4 b0 = *(const float4*)(brow);
                float4 b1 = *(const float4*)(brow + 4);
                bd[0] = pk2(b0.x, b0.x); bd[1] = pk2(b0.y, b0.y);
                bd[2] = pk2(b0.z, b0.z); bd[3] = pk2(b0.w, b0.w);
                bd[4] = pk2(b1.x, b1.x); bd[5] = pk2(b1.y, b1.y);
                bd[6] = pk2(b1.z, b1.z); bd[7] = pk2(b1.w, b1.w);
            } else if constexpr (TN == 4) {
                float4 b0 = *(const float4*)(brow);
                bd[0] = pk2(b0.x, b0.x); bd[1] = pk2(b0.y, b0.y);
                bd[2] = pk2(b0.z, b0.z); bd[3] = pk2(b0.w, b0.w);
            } else {
                float2 b0 = *(const float2*)(brow);
                bd[0] = pk2(b0.x, b0.x); bd[1] = pk2(b0.y, b0.y);
            }
            const float* Ar = AsF + k * BM;
            ulonglong2 a0 = *(const ulonglong2*)(Ar + ((ty * 8)     ^ msk));
            ulonglong2 a1 = *(const ulonglong2*)(Ar + ((ty * 8 + 4) ^ msk));
            u64 ap[4] = { a0.x, a0.y, a1.x, a1.y };
#pragma unroll
            for (int j = 0; j < TN; ++j)
#pragma unroll
                for (int i = 0; i < 4; ++i)
                    acc[i][j] = ffma2(ap[i], bd[j], acc[i][j]);
        }
        __syncthreads();
    }

    // store partials (pure fp32, no epilogue math)
#pragma unroll
    for (int r = 0; r < 8; ++r) {
        float v[TN];
#pragma unroll
        for (int j = 0; j < TN; ++j) {
            float lo, hi; upk2(acc[r >> 1][j], lo, hi);
            v[j] = (r & 1) ? hi : lo;
        }
        float* dst = outp + (size_t)(tile * BM + ty * 8 + r) * D + tx * TN;
        if constexpr (TN == 8) {
            *(float4*)dst       = make_float4(v[0], v[1], v[2], v[3]);
            *(float4*)(dst + 4) = make_float4(v[4], v[5], v[6], v[7]);
        } else if constexpr (TN == 4) {
            *(float4*)dst = make_float4(v[0], v[1], v[2], v[3]);
        } else {
            *(float2*)dst = make_float2(v[0], v[1]);
        }
    }
}

__global__ void __launch_bounds__(NTHR, 3) gemm_splitk(
    const float* __restrict__ x0, const float* __restrict__ w0,
    const float* __restrict__ x1, const float* __restrict__ w1,
    const float* __restrict__ x2, const float* __restrict__ w2,
    const float* __restrict__ x3, const float* __restrict__ w3)
{
    __shared__ __align__(16) float AsF[BK * BM];     // 8 KB
    __shared__ __align__(16) float Bk[BK * 72];      // 4.5 KB
    const int bid   = blockIdx.x;                    // 512 blocks
    const int s     = bid & 3;                       // stream interleave
    const int split = (bid >> 2) & 1;
    const int tile  = bid >> 3;                      // 64 tiles per stream
    float* part = g_part[split];
    if (s == 0)      run_gemm<64>(x0, w0, tile, split, AsF, Bk, part);
    else if (s == 1) run_gemm<32>(x1, w1, tile, split, AsF, Bk, part + BASE1);
    else if (s == 2) run_gemm<32>(x2, w2, tile, split, AsF, Bk, part + BASE2);
    else             run_gemm<16>(x3, w3, tile, split, AsF, Bk, part + BASE3);
}

// One warp per output row: sum partials + bias -> exact GELU -> LN -> gamma/beta.
__global__ void __launch_bounds__(256) combine_ln(
    const float* __restrict__ b0, const float* __restrict__ g0, const float* __restrict__ t0,
    const float* __restrict__ b1, const float* __restrict__ g1, const float* __restrict__ t1,
    const float* __restrict__ b2, const float* __restrict__ g2, const float* __restrict__ t2,
    const float* __restrict__ b3, const float* __restrict__ g3, const float* __restrict__ t3,
    float* __restrict__ out)
{
    const int rid  = blockIdx.x * 8 + (threadIdx.x >> 5);   // 0..32767
    const int lane = threadIdx.x & 31;
    const int s = rid >> 13;
    const int m = rid & 8191;
    int D; size_t base; const float *Bp, *Gp, *Tp;
    if (s == 0)      { D = 64; base = 0;     Bp = b0; Gp = g0; Tp = t0; }
    else if (s == 1) { D = 32; base = BASE1; Bp = b1; Gp = g1; Tp = t1; }
    else if (s == 2) { D = 32; base = BASE2; Bp = b2; Gp = g2; Tp = t2; }
    else             { D = 16; base = BASE3; Bp = b3; Gp = g3; Tp = t3; }
    const size_t off = base + (size_t)m * D;

    const bool act0 = lane < D;
    const bool act1 = (D == 64);
    const int  c1   = lane + 32;
    float v0 = 0.f, v1 = 0.f;
    if (act0) {
        float x = g_part[0][off + lane] + g_part[1][off + lane] + Bp[lane];
        v0 = 0.5f * x * (1.0f + erff(x * 0.7071067811865475f));
    }
    if (act1) {
        float x = g_part[0][off + c1] + g_part[1][off + c1] + Bp[c1];
        v1 = 0.5f * x * (1.0f + erff(x * 0.7071067811865475f));
    }
    float ss = v0 + v1, s2 = v0 * v0 + v1 * v1;
#pragma unroll
    for (int o = 16; o >= 1; o >>= 1) {
        ss += __shfl_xor_sync(0xffffffffu, ss, o);
        s2 += __shfl_xor_sync(0xffffffffu, s2, o);
    }
    const float invD = 1.0f / (float)D;
    float mu  = ss * invD;
    float var = fmaxf(s2 * invD - mu * mu, 0.0f);
    float rs  = rsqrtf(var + 1e-5f);
    if (act0) out[off + lane] = (v0 - mu) * rs * Gp[lane] + Tp[lane];
    if (act1) out[off + c1]   = (v1 - mu) * rs * Gp[c1]   + Tp[c1];
}

extern "C" void kernel_launch(void* const* d_in, const int* in_sizes, int n_in,
                              void* d_out, int out_size)
{
    const float* x0 = (const float*)d_in[0];
    const float* w0 = (const float*)d_in[1];
    const float* b0 = (const float*)d_in[2];
    const float* g0 = (const float*)d_in[3];
    const float* t0 = (const float*)d_in[4];
    const float* x1 = (const float*)d_in[5];
    const float* w1 = (const float*)d_in[6];
    const float* b1 = (const float*)d_in[7];
    const float* g1 = (const float*)d_in[8];
    const float* t1 = (const float*)d_in[9];
    const float* x2 = (const float*)d_in[10];
    const float* w2 = (const float*)d_in[11];
    const float* b2 = (const float*)d_in[12];
    const float* g2 = (const float*)d_in[13];
    const float* t2 = (const float*)d_in[14];
    const float* x3 = (const float*)d_in[15];
    const float* w3 = (const float*)d_in[16];
    const float* b3 = (const float*)d_in[17];
    const float* g3 = (const float*)d_in[18];
    const float* t3 = (const float*)d_in[19];
    float* out = (float*)d_out;

    // Kernel 1: split-K GEMM, 512 blocks x 128 threads, BK=16, no reg cap squeeze
    gemm_splitk<<<512, NTHR>>>(x0, w0, x1, w1, x2, w2, x3, w3);
    // Kernel 2: combine + bias + GELU + LayerNorm, one warp per row
    combine_ln<<<4096, 256>>>(b0, g0, t0, b1, g1, t1, b2, g2, t2, b3, g3, t3, out);
}

// round 16
// speedup vs baseline: 2.2306x; 1.8042x over previous
#include <cuda_runtime.h>
#include <cuda_bf16.h>
#include <math.h>
#include <stdint.h>

#define HIN  1536
#define BKC  64
#define NCH  (HIN / BKC)
#define NTHR 128

#define BASE1 524288
#define BASE2 786432
#define BASE3 1048576

__device__ __nv_bfloat16 g_wt_hi[144 * HIN];
__device__ __nv_bfloat16 g_wt_lo[144 * HIN];

typedef unsigned long long u64;

__device__ __forceinline__ uint32_t smem_u32(const void* p) {
    uint32_t a;
    asm("{ .reg .u64 t; cvta.to.shared.u64 t, %1; cvt.u32.u64 %0, t; }" : "=r"(a) : "l"(p));
    return a;
}

// 128B-row swizzle: XOR 3 row bits into the 16B-column bits
__device__ __forceinline__ int swz(int off) {
    return off ^ (((off >> 7) & 7) << 4);
}

// pack bf16x2: low half = a, high half = b
__device__ __forceinline__ uint32_t cvt2(float a, float b) {
    uint32_t w;
    asm("cvt.rn.satfinite.bf16x2.f32 %0, %1, %2;" : "=r"(w) : "f"(b), "f"(a));
    return w;
}

__device__ __forceinline__ void ldsm4(uint32_t* r, uint32_t addr) {
    asm volatile("ldmatrix.sync.aligned.m8n8.x4.shared.b16 {%0,%1,%2,%3}, [%4];"
                 : "=r"(r[0]), "=r"(r[1]), "=r"(r[2]), "=r"(r[3]) : "r"(addr));
}

__device__ __forceinline__ void mma_bf16(float* c, const uint32_t* a, const uint32_t* b) {
    asm volatile(
        "mma.sync.aligned.m16n8k16.row.col.f32.bf16.bf16.f32 "
        "{%0,%1,%2,%3}, {%4,%5,%6,%7}, {%8,%9}, {%0,%1,%2,%3};"
        : "+f"(c[0]), "+f"(c[1]), "+f"(c[2]), "+f"(c[3])
        : "r"(a[0]), "r"(a[1]), "r"(a[2]), "r"(a[3]), "r"(b[0]), "r"(b[1]));
}

// A fragment address (m16k16, row-major): matrices [m0..7,k0][m8..15,k0][m0..7,k0+8][m8..15,k0+8]
__device__ __forceinline__ uint32_t a_addr(uint32_t base, int mt, int kk, int lane) {
    int off = (mt + (lane & 15)) * 128 + kk * 32 + ((lane >> 4) << 4);
    return base + swz(off);
}
// B fragment address (two adjacent n8 tiles per x4): rows = n, cols = k
__device__ __forceinline__ uint32_t b_addr(uint32_t base, int n0, int kk, int lane) {
    int row = n0 + (lane & 7) + (((lane >> 4) & 1) << 3);
    int off = row * 128 + kk * 32 + (((lane >> 3) & 1) << 4);
    return base + swz(off);
}

// ---------------- Pre-kernel: W -> transposed bf16 hi/lo ----------------

__global__ void convert_w(const float* __restrict__ w0, const float* __restrict__ w1,
                          const float* __restrict__ w2, const float* __restrict__ w3)
{
    int idx = blockIdx.x * 256 + threadIdx.x;
    if (idx >= 144 * HIN) return;
    int n = idx / HIN;
    int k = idx - n * HIN;
    const float* W;
    int D, nl;
    if (n < 64)       { W = w0; D = 64; nl = n; }
    else if (n < 96)  { W = w1; D = 32; nl = n - 64; }
    else if (n < 128) { W = w2; D = 32; nl = n - 96; }
    else              { W = w3; D = 16; nl = n - 128; }
    float v = W[(size_t)k * D + nl];
    __nv_bfloat16 h = __float2bfloat16(v);
    float r = v - __bfloat162float(h);
    g_wt_hi[idx] = h;
    g_wt_lo[idx] = __float2bfloat16(r);
}

// ---------------- Main kernel: bf16-split HMMA GEMM + fused epilogue ----------------
// smem (static 48KB): Ah[16K] Al[16K] Bh[N*128] Bl[N*128]

template<int N>
__device__ void tile_mma(const float* __restrict__ X, int nbase,
                         const float* __restrict__ Bias, const float* __restrict__ Gam,
                         const float* __restrict__ Bet, float* __restrict__ OUT,
                         int tile, char* __restrict__ smem)
{
    constexpr int NT8 = N / 8;     // n8 tiles: 8/4/2
    constexpr int NBQ = N / 8;     // B uint4 per thread per chunk
    const int tid = threadIdx.x;
    const int wid = tid >> 5;
    const int lane = tid & 31;

    char* Ah = smem;
    char* Al = smem + 16384;
    char* Bh = smem + 32768;
    char* Bl = smem + 32768 + N * 128;
    const uint32_t ah_u = smem_u32(Ah);
    const uint32_t al_u = smem_u32(Al);
    const uint32_t bh_u = smem_u32(Bh);
    const uint32_t bl_u = smem_u32(Bl);

    const float* __restrict__ Ablk = X + (size_t)tile * 128 * HIN;
    const __nv_bfloat16* __restrict__ WH = g_wt_hi + (size_t)nbase * HIN;
    const __nv_bfloat16* __restrict__ WL = g_wt_lo + (size_t)nbase * HIN;

    float acc[2][NT8][4];
#pragma unroll
    for (int t = 0; t < 2; ++t)
#pragma unroll
        for (int nt = 0; nt < NT8; ++nt)
#pragma unroll
            for (int j = 0; j < 4; ++j) acc[t][nt][j] = 0.f;

    float4 va[16];
    uint4 vbq[NBQ];

    // prologue: chunk 0
#pragma unroll
    for (int i = 0; i < 16; ++i) {
        int f4 = tid + i * 128;
        int row = f4 >> 4, c4 = f4 & 15;
        va[i] = *(const float4*)(Ablk + (size_t)row * HIN + c4 * 4);
    }
#pragma unroll
    for (int q = 0; q < NBQ; ++q) {
        int f4 = tid + q * 128;
        int rowid = f4 >> 3, col = f4 & 7;
        const __nv_bfloat16* src = (rowid < N) ? (WH + (size_t)rowid * HIN)
                                               : (WL + (size_t)(rowid - N) * HIN);
        vbq[q] = *(const uint4*)(src + col * 8);
    }

    const int mt0 = wid * 32;

    for (int c = 0; c < NCH; ++c) {
        __syncthreads();   // previous chunk's ldmatrix reads complete

        // convert + store A hi/lo
#pragma unroll
        for (int i = 0; i < 16; ++i) {
            int f4 = tid + i * 128;
            int row = f4 >> 4, c4 = f4 & 15;
            float4 v = va[i];
            uint32_t h01 = cvt2(v.x, v.y);
            uint32_t h23 = cvt2(v.z, v.w);
            float hx = __uint_as_float(h01 << 16);
            float hy = __uint_as_float(h01 & 0xffff0000u);
            float hz = __uint_as_float(h23 << 16);
            float hw = __uint_as_float(h23 & 0xffff0000u);
            uint32_t l01 = cvt2(v.x - hx, v.y - hy);
            uint32_t l23 = cvt2(v.z - hz, v.w - hw);
            int ph = swz(row * 128 + c4 * 8);
            *(u64*)(Ah + ph) = (u64)h01 | ((u64)h23 << 32);
            *(u64*)(Al + ph) = (u64)l01 | ((u64)l23 << 32);
        }
        // store B hi/lo
#pragma unroll
        for (int q = 0; q < NBQ; ++q) {
            int f4 = tid + q * 128;
            int rowid = f4 >> 3, col = f4 & 7;
            char* dst = (rowid < N) ? Bh : Bl;
            int n = (rowid < N) ? rowid : rowid - N;
            *(uint4*)(dst + swz(n * 128 + col * 16)) = vbq[q];
        }
        __syncthreads();

        // prefetch next chunk (LDG latency overlaps the mma block below)
        if (c + 1 < NCH) {
            const int cb = (c + 1) * BKC;
#pragma unroll
            for (int i = 0; i < 16; ++i) {
                int f4 = tid + i * 128;
                int row = f4 >> 4, c4 = f4 & 15;
                va[i] = *(const float4*)(Ablk + (size_t)row * HIN + cb + c4 * 4);
            }
#pragma unroll
            for (int q = 0; q < NBQ; ++q) {
                int f4 = tid + q * 128;
                int rowid = f4 >> 3, col = f4 & 7;
                const __nv_bfloat16* src = (rowid < N) ? (WH + (size_t)rowid * HIN)
                                                       : (WL + (size_t)(rowid - N) * HIN);
                vbq[q] = *(const uint4*)(src + cb + col * 8);
            }
        }

        // compute: 4 k16 steps
#pragma unroll
        for (int kk = 0; kk < 4; ++kk) {
            uint32_t afh[2][4], afl[2][4];
#pragma unroll
            for (int t = 0; t < 2; ++t) {
                ldsm4(afh[t], a_addr(ah_u, mt0 + t * 16, kk, lane));
                ldsm4(afl[t], a_addr(al_u, mt0 + t * 16, kk, lane));
            }
#pragma unroll
            for (int p = 0; p < NT8 / 2; ++p) {
                uint32_t bfh[4], bfl[4];
                ldsm4(bfh, b_addr(bh_u, p * 16, kk, lane));
                ldsm4(bfl, b_addr(bl_u, p * 16, kk, lane));
#pragma unroll
                for (int t = 0; t < 2; ++t) {
                    mma_bf16(acc[t][2 * p],     afh[t], bfh);
                    mma_bf16(acc[t][2 * p],     afh[t], bfl);
                    mma_bf16(acc[t][2 * p],     afl[t], bfh);
                    mma_bf16(acc[t][2 * p + 1], afh[t], bfh + 2);
                    mma_bf16(acc[t][2 * p + 1], afh[t], bfl + 2);
                    mma_bf16(acc[t][2 * p + 1], afl[t], bfh + 2);
                }
            }
        }
    }

    // ---- fused epilogue ----
    // fragment: acc[t][nt][h*2+j] = D[m = mt0 + t*16 + h*8 + g][n = nt*8 + tg*2 + j]
    const int g = lane >> 2;
    const int tg = lane & 3;
    const float invD = 1.0f / (float)N;
#pragma unroll
    for (int t = 0; t < 2; ++t) {
#pragma unroll
        for (int h = 0; h < 2; ++h) {
            float vv[2 * NT8];
            float s = 0.f, s2 = 0.f;
#pragma unroll
            for (int nt = 0; nt < NT8; ++nt) {
#pragma unroll
                for (int j = 0; j < 2; ++j) {
                    int n = nt * 8 + tg * 2 + j;
                    float x = acc[t][nt][h * 2 + j] + __ldg(Bias + n);
                    float gl = 0.5f * x * (1.0f + erff(x * 0.7071067811865475f));
                    vv[nt * 2 + j] = gl;
                    s += gl;
                    s2 += gl * gl;
                }
            }
            s  += __shfl_xor_sync(0xffffffffu, s, 1);
            s  += __shfl_xor_sync(0xffffffffu, s, 2);
            s2 += __shfl_xor_sync(0xffffffffu, s2, 1);
            s2 += __shfl_xor_sync(0xffffffffu, s2, 2);
            float mu = s * invD;
            float var = fmaxf(s2 * invD - mu * mu, 0.0f);
            float rs = rsqrtf(var + 1e-5f);
            int m = tile * 128 + mt0 + t * 16 + h * 8 + g;
            float* dst = OUT + (size_t)m * N;
#pragma unroll
            for (int nt = 0; nt < NT8; ++nt) {
                int n = nt * 8 + tg * 2;
                float2 o;
                o.x = (vv[nt * 2]     - mu) * rs * __ldg(Gam + n)     + __ldg(Bet + n);
                o.y = (vv[nt * 2 + 1] - mu) * rs * __ldg(Gam + n + 1) + __ldg(Bet + n + 1);
                *(float2*)(dst + n) = o;
            }
        }
    }
}

__global__ void __launch_bounds__(NTHR, 2) gemm_mma(
    const float* __restrict__ x0, const float* __restrict__ b0,
    const float* __restrict__ g0, const float* __restrict__ t0,
    const float* __restrict__ x1, const float* __restrict__ b1,
    const float* __restrict__ g1, const float* __restrict__ t1,
    const float* __restrict__ x2, const float* __restrict__ b2,
    const float* __restrict__ g2, const float* __restrict__ t2,
    const float* __restrict__ x3, const float* __restrict__ b3,
    const float* __restrict__ g3, const float* __restrict__ t3,
    float* __restrict__ out)
{
    __shared__ __align__(128) char smem[49152];
    const int bid = blockIdx.x;
    const int s = bid >> 6;
    const int tile = bid & 63;
    if (s == 0) {
        tile_mma<64>(x0, 0, b0, g0, t0, out, tile, smem);
    } else if (s == 1) {
        tile_mma<32>(x1, 64, b1, g1, t1, out + BASE1, tile, smem);
    } else if (s == 2) {
        tile_mma<32>(x2, 96, b2, g2, t2, out + BASE2, tile, smem);
    } else {
        tile_mma<16>(x3, 128, b3, g3, t3, out + BASE3, tile, smem);
    }
}

extern "C" void kernel_launch(void* const* d_in, const int* in_sizes, int n_in,
                              void* d_out, int out_size)
{
    const float* x0 = (const float*)d_in[0];
    const float* w0 = (const float*)d_in[1];
    const float* b0 = (const float*)d_in[2];
    const float* g0 = (const float*)d_in[3];
    const float* t0 = (const float*)d_in[4];
    const float* x1 = (const float*)d_in[5];
    const float* w1 = (const float*)d_in[6];
    const float* b1 = (const float*)d_in[7];
    const float* g1 = (const float*)d_in[8];
    const float* t1 = (const float*)d_in[9];
    const float* x2 = (const float*)d_in[10];
    const float* w2 = (const float*)d_in[11];
    const float* b2 = (const float*)d_in[12];
    const float* g2 = (const float*)d_in[13];
    const float* t2 = (const float*)d_in[14];
    const float* x3 = (const float*)d_in[15];
    const float* w3 = (const float*)d_in[16];
    const float* b3 = (const float*)d_in[17];
    const float* g3 = (const float*)d_in[18];
    const float* t3 = (const float*)d_in[19];
    float* out = (float*)d_out;

    convert_w<<<(144 * HIN + 255) / 256, 256>>>(w0, w1, w2, w3);
    gemm_mma<<<256, NTHR>>>(
        x0, b0, g0, t0, x1, b1, g1, t1,
        x2, b2, g2, t2, x3, b3, g3, t3, out);
}